// round 15
// baseline (speedup 1.0000x reference)
#include <cuda_runtime.h>
#include <cuda_fp16.h>
#include <cstdint>

// ---------------- problem constants ----------------
#define T_CO 16
#define BATCH 16
#define NH 28
#define NW 28
#define CCH 64
#define KCH 64
#define ROW_FLOATS (NW * CCH)                  // 1792
#define TRANS_T_STRIDE (BATCH * NH * NW * CCH) // 802816
#define TRANS_B_STRIDE (NH * NW * CCH)         // 50176

#define NTHREADS 1024

// per-t smem slot (bytes): A tile fp16 (32 rows x 144B = 4608) during GEMM,
// then reused as mix[t] full row (28 rows x 272B = 7616).
#define AROW 144
#define MIX_ROW 272                            // 68 words; 68 % 32 == 4 (2-way max)
#define SLOT 7680
#define SMEM_BYTES (T_CO * SLOT)               // 122880 -> 1 CTA/SM (RF-bound anyway)

// ---------------- weight fragments (prepacked fp16, single-rounded) ---------
// layout [s][t][kt 4][ntp 4][lane 32] x uint4
//   uint4 = { nt=2*ntp : (b0,b1),  nt=2*ntp+1 : (b0,b1) }
__device__ uint32_t g_wfrag[2 * T_CO * 4 * 4 * 32 * 4];   // 256 KB

__device__ __forceinline__ uint32_t pack_f16x2(float lo_elem, float hi_elem) {
    uint32_t r;
    asm("cvt.rn.f16x2.f32 %0, %1, %2;" : "=r"(r) : "f"(hi_elem), "f"(lo_elem));
    return r;
}

// one block per (s,t): coalesced load of W[t] into smem, then fragment gen
__global__ void prep_weights(const float* __restrict__ w1, const float* __restrict__ w2) {
    __shared__ float sw[64 * 64];              // [c][k]
    const int s = blockIdx.x >> 4;
    const int t = blockIdx.x & 15;
    const float* w = (s ? w2 : w1) + (size_t)t * 4096;
    const int tid = threadIdx.x;               // 256
    #pragma unroll
    for (int i = 0; i < 16; i++) sw[i * 256 + tid] = w[i * 256 + tid];
    __syncthreads();

    uint4* dst = (uint4*)g_wfrag + (size_t)(s * T_CO + t) * 512;
    #pragma unroll
    for (int q = 0; q < 2; q++) {
        int fid  = tid * 2 + q;                // 0..511
        int lane = fid & 31;
        int ntp  = (fid >> 5) & 3;
        int kt   = fid >> 7;
        int k0   = (ntp * 2) * 8 + (lane >> 2);
        int k1   = k0 + 8;
        int c    = kt * 16 + (lane & 3) * 2;
        uint4 o;
        o.x = pack_f16x2(sw[c * 64 + k0],       sw[(c + 1) * 64 + k0]);
        o.y = pack_f16x2(sw[(c + 8) * 64 + k0], sw[(c + 9) * 64 + k0]);
        o.z = pack_f16x2(sw[c * 64 + k1],       sw[(c + 1) * 64 + k1]);
        o.w = pack_f16x2(sw[(c + 8) * 64 + k1], sw[(c + 9) * 64 + k1]);
        dst[(kt * 4 + ntp) * 32 + lane] = o;
    }
}

// ---------------- main kernel ----------------
__device__ __forceinline__ float2 f2add(float2 a, float2 b) { return make_float2(a.x + b.x, a.y + b.y); }
__device__ __forceinline__ float2 f2sub(float2 a, float2 b) { return make_float2(a.x - b.x, a.y - b.y); }

__device__ __forceinline__ uint32_t smem_u32(const void* p) {
    uint32_t a;
    asm("{ .reg .u64 t; cvta.to.shared.u64 t, %1; cvt.u32.u64 %0, t; }" : "=r"(a) : "l"(p));
    return a;
}

__device__ __forceinline__ void ldmatrix_x4(uint32_t& r0, uint32_t& r1,
                                            uint32_t& r2, uint32_t& r3,
                                            uint32_t saddr) {
    asm volatile("ldmatrix.sync.aligned.m8n8.x4.shared.b16 {%0,%1,%2,%3}, [%4];"
                 : "=r"(r0), "=r"(r1), "=r"(r2), "=r"(r3) : "r"(saddr));
}

#define MMA4(d, a0, a1, a2, a3, b0, b1)                                      \
    asm("mma.sync.aligned.m16n8k16.row.col.f32.f16.f16.f32 "                 \
        "{%0,%1,%2,%3},{%4,%5,%6,%7},{%8,%9},{%0,%1,%2,%3};"                 \
        : "+f"((d)[0]), "+f"((d)[1]), "+f"((d)[2]), "+f"((d)[3])             \
        : "r"(a0), "r"(a1), "r"(a2), "r"(a3), "r"(b0), "r"(b1))

__global__ void __launch_bounds__(NTHREADS, 1)
iwht2_mma_kernel(const float* __restrict__ tr1, const float* __restrict__ tr2,
                 const float* __restrict__ b1,  const float* __restrict__ b2,
                 float* __restrict__ out, size_t out_stream_stride)
{
    extern __shared__ char smc[];

    // CTA = (s, b, h)
    const int bi  = blockIdx.x;
    const int s   = bi / (BATCH * NH);
    const int rem = bi - s * (BATCH * NH);
    const int b   = rem / NH;
    const int h   = rem - b * NH;

    const float* tr = s ? tr2 : tr1;
    const float* bs = s ? b2  : b1;
    float* outp = out + (size_t)s * out_stream_stride;

    const int tid   = threadIdx.x;
    const int wrp   = tid >> 5;           // warp 0..31
    const int t     = wrp >> 1;           // coefficient
    const int khalf = wrp & 1;            // n-half
    const int lane  = tid & 31;
    const int lane64 = tid & 63;
    const int g    = lane >> 2;
    const int tg   = lane & 3;
    const int barid = 1 + (t >> 1);       // quad barrier ids 1..8
    char* tslot = smc + t * SLOT;

    // B fragment base: [kt][ntp][lane] uint4; this warp uses ntp = khalf*2, +1
    const char* gw = (const char*)g_wfrag
                   + (size_t)(s * T_CO + t) * 8192
                   + (size_t)(khalf * 2 * 32 + lane) * 16;

    // prefetch kt=0 B fragments; staging hides the latency
    uint4 bc0 = *(const uint4*)(gw);
    uint4 bc1 = *(const uint4*)(gw + 512);

    // ---- stage A (shared by the khalf pair): trans tile -> fp16, 144B rows ----
    {
        const float4* gsrc = (const float4*)(tr + (size_t)b * TRANS_B_STRIDE
                                                + (size_t)h * ROW_FLOATS
                                                + (size_t)t * TRANS_T_STRIDE);
        #pragma unroll
        for (int i = 0; i < 7; i++) {
            int idx = i * 64 + lane64;         // 0..447 float4s
            int row = idx >> 4;
            int c4  = idx & 15;
            float4 v = __ldg(gsrc + idx);
            uint2 hh;
            hh.x = pack_f16x2(v.x, v.y);
            hh.y = pack_f16x2(v.z, v.w);
            *(uint2*)(tslot + row * AROW + c4 * 8) = hh;
        }
    }
    // quad barrier: A tiles staged before fragments are read
    asm volatile("bar.sync %0, 128;" :: "r"(barid) : "memory");

    // ---- GEMM: D(28x32slice) = A(28x64 fp16) x B(64x32slice fp16) ----
    float acc[2][4][4];
    #pragma unroll
    for (int mt = 0; mt < 2; mt++)
        #pragma unroll
        for (int nt = 0; nt < 4; nt++)
            #pragma unroll
            for (int j = 0; j < 4; j++) acc[mt][nt][j] = 0.0f;

    const uint32_t abase0 = smem_u32(tslot)
                          + ((lane & 7) + ((lane >> 3) & 1) * 8) * AROW
                          + ((lane >> 4)) * 16;
    const uint32_t abase1 = abase0 + 16 * AROW;

    #pragma unroll 1
    for (int kt = 0; kt < 4; kt++) {
        uint32_t a00, a01, a02, a03, a10, a11, a12, a13;
        ldmatrix_x4(a00, a01, a02, a03, abase0 + kt * 32);
        ldmatrix_x4(a10, a11, a12, a13, abase1 + kt * 32);

        MMA4(acc[0][0], a00, a01, a02, a03, bc0.x, bc0.y);
        MMA4(acc[1][0], a10, a11, a12, a13, bc0.x, bc0.y);
        MMA4(acc[0][1], a00, a01, a02, a03, bc0.z, bc0.w);
        MMA4(acc[1][1], a10, a11, a12, a13, bc0.z, bc0.w);
        MMA4(acc[0][2], a00, a01, a02, a03, bc1.x, bc1.y);
        MMA4(acc[1][2], a10, a11, a12, a13, bc1.x, bc1.y);
        MMA4(acc[0][3], a00, a01, a02, a03, bc1.z, bc1.w);
        MMA4(acc[1][3], a10, a11, a12, a13, bc1.z, bc1.w);

        if (kt < 3) {
            bc0 = *(const uint4*)(gw + (kt + 1) * 2048);
            bc1 = *(const uint4*)(gw + (kt + 1) * 2048 + 512);
        }
    }

    // quad barrier: all 4 warps done reading A before D overwrites the slots
    asm volatile("bar.sync %0, 128;" :: "r"(barid) : "memory");

    // ---- write D into mix slot (kp = khalf*16 + nt*4 + tg, full 64-k rows) ----
    #pragma unroll
    for (int mt = 0; mt < 2; mt++) {
        #pragma unroll
        for (int nt = 0; nt < 4; nt++) {
            int row0 = mt * 16 + g;
            int kp   = khalf * 16 + nt * 4 + tg;
            *(float2*)(tslot + row0 * MIX_ROW + kp * 8) =
                make_float2(acc[mt][nt][0], acc[mt][nt][1]);
            int row1 = row0 + 8;
            if (row1 < 28)
                *(float2*)(tslot + row1 * MIX_ROW + kp * 8) =
                    make_float2(acc[mt][nt][2], acc[mt][nt][3]);
        }
    }
    __syncthreads();

    // ---- combine: inverse 2D 4-pt WHT over t = 4u+v, scale 1/16, + bias ----
    if (tid < 896) {                       // w(28) x kpair(32)
        const int wrow = tid >> 5;
        const int kp   = tid & 31;

        float2 m[16];
        #pragma unroll
        for (int tt = 0; tt < 16; tt++)
            m[tt] = *(const float2*)(smc + tt * SLOT + wrow * MIX_ROW + kp * 8);

        #pragma unroll
        for (int u = 0; u < 4; u++) {
            float2 m0 = m[4*u], m1 = m[4*u+1], m2 = m[4*u+2], m3 = m[4*u+3];
            float2 s0 = f2add(m0, m1), d0 = f2sub(m0, m1);
            float2 s1 = f2add(m2, m3), d1 = f2sub(m2, m3);
            m[4*u + 0] = f2add(s0, s1);
            m[4*u + 1] = f2add(d0, d1);
            m[4*u + 2] = f2sub(s0, s1);
            m[4*u + 3] = f2sub(d0, d1);
        }

        const float2 bv = ((const float2*)bs)[kp];
        float* op = outp + (size_t)b * (112 * 112 * 64)
                         + (size_t)h * (4 * 112 * 64)
                         + (size_t)wrow * (4 * 64)
                         + 2 * kp;

        #pragma unroll
        for (int j = 0; j < 4; j++) {
            float2 r0 = m[j], r1 = m[4 + j], r2 = m[8 + j], r3 = m[12 + j];
            float2 s0 = f2add(r0, r1), d0 = f2sub(r0, r1);
            float2 s1 = f2add(r2, r3), d1 = f2sub(r2, r3);
            float2 o0 = f2add(s0, s1);
            float2 o1 = f2add(d0, d1);
            float2 o2 = f2sub(s0, s1);
            float2 o3 = f2sub(d0, d1);
            float2 v0 = make_float2(fmaf(o0.x, 0.0625f, bv.x), fmaf(o0.y, 0.0625f, bv.y));
            float2 v1 = make_float2(fmaf(o1.x, 0.0625f, bv.x), fmaf(o1.y, 0.0625f, bv.y));
            float2 v2 = make_float2(fmaf(o2.x, 0.0625f, bv.x), fmaf(o2.y, 0.0625f, bv.y));
            float2 v3 = make_float2(fmaf(o3.x, 0.0625f, bv.x), fmaf(o3.y, 0.0625f, bv.y));
            *reinterpret_cast<float2*>(op + 0 * 7168 + j * 64) = v0;
            *reinterpret_cast<float2*>(op + 1 * 7168 + j * 64) = v1;
            *reinterpret_cast<float2*>(op + 2 * 7168 + j * 64) = v2;
            *reinterpret_cast<float2*>(op + 3 * 7168 + j * 64) = v3;
        }
    }
}

extern "C" void kernel_launch(void* const* d_in, const int* in_sizes, int n_in,
                              void* d_out, int out_size) {
    (void)in_sizes; (void)n_in;
    const float* tr1 = (const float*)d_in[0];
    const float* tr2 = (const float*)d_in[1];
    const float* w1  = (const float*)d_in[2];
    const float* w2  = (const float*)d_in[3];
    const float* b1  = (const float*)d_in[4];
    const float* b2  = (const float*)d_in[5];
    float* out = (float*)d_out;

    prep_weights<<<32, 256>>>(w1, w2);

    cudaFuncSetAttribute(iwht2_mma_kernel,
                         cudaFuncAttributeMaxDynamicSharedMemorySize, SMEM_BYTES);
    size_t stream_stride = (size_t)out_size / 2;   // out1 then out2
    iwht2_mma_kernel<<<2 * BATCH * NH, NTHREADS, SMEM_BYTES>>>(
        tr1, tr2, b1, b2, out, stream_stride);
}

// round 16
// speedup vs baseline: 1.1410x; 1.1410x over previous
#include <cuda_runtime.h>
#include <cuda_fp16.h>
#include <cstdint>

// ---------------- problem constants ----------------
#define T_CO 16
#define BATCH 16
#define NH 28
#define NW 28
#define CCH 64
#define KCH 64
#define ROW_FLOATS (NW * CCH)                  // 1792
#define TRANS_T_STRIDE (BATCH * NH * NW * CCH) // 802816
#define TRANS_B_STRIDE (NH * NW * CCH)         // 50176

#define NTHREADS 512

// per-t smem slot (bytes): A tile fp16, linear layout, 144B-padded rows
// (32 row slots so tile-1 fragment reads stay in-bounds); reused as fp16 mix
// slice (28 rows x 72B).
#define AROW 144
#define SLOT 4608
#define SMEM_BYTES (T_CO * SLOT)               // 73728 -> 2 CTAs/SM
#define MIX_ROW 72                             // fp16 mix: 32 k x 2B + 8B pad

// ---------------- weight fragments (prepacked fp16, single-rounded) ---------
// layout [s][t][kt 4][ntp 4][lane 32] x uint4
//   uint4 = { nt=2*ntp : (b0,b1),  nt=2*ntp+1 : (b0,b1) }
__device__ uint32_t g_wfrag[2 * T_CO * 4 * 4 * 32 * 4];   // 256 KB

__device__ __forceinline__ uint32_t pack_f16x2(float lo_elem, float hi_elem) {
    uint32_t r;
    asm("cvt.rn.f16x2.f32 %0, %1, %2;" : "=r"(r) : "f"(hi_elem), "f"(lo_elem));
    return r;
}

// one block per (s,t): coalesced load of W[t] into smem, then fragment gen
__global__ void prep_weights(const float* __restrict__ w1, const float* __restrict__ w2) {
    __shared__ float sw[64 * 64];              // [c][k]
    const int s = blockIdx.x >> 4;
    const int t = blockIdx.x & 15;
    const float* w = (s ? w2 : w1) + (size_t)t * 4096;
    const int tid = threadIdx.x;               // 256
    #pragma unroll
    for (int i = 0; i < 16; i++) sw[i * 256 + tid] = w[i * 256 + tid];
    __syncthreads();

    uint4* dst = (uint4*)g_wfrag + (size_t)(s * T_CO + t) * 512;
    #pragma unroll
    for (int q = 0; q < 2; q++) {
        int fid  = tid * 2 + q;                // 0..511
        int lane = fid & 31;
        int ntp  = (fid >> 5) & 3;
        int kt   = fid >> 7;
        int k0   = (ntp * 2) * 8 + (lane >> 2);
        int k1   = k0 + 8;
        int c    = kt * 16 + (lane & 3) * 2;
        uint4 o;
        o.x = pack_f16x2(sw[c * 64 + k0],       sw[(c + 1) * 64 + k0]);
        o.y = pack_f16x2(sw[(c + 8) * 64 + k0], sw[(c + 9) * 64 + k0]);
        o.z = pack_f16x2(sw[c * 64 + k1],       sw[(c + 1) * 64 + k1]);
        o.w = pack_f16x2(sw[(c + 8) * 64 + k1], sw[(c + 9) * 64 + k1]);
        dst[(kt * 4 + ntp) * 32 + lane] = o;
    }
}

// ---------------- main kernel ----------------
__device__ __forceinline__ float2 f2add(float2 a, float2 b) { return make_float2(a.x + b.x, a.y + b.y); }
__device__ __forceinline__ float2 f2sub(float2 a, float2 b) { return make_float2(a.x - b.x, a.y - b.y); }

__device__ __forceinline__ uint32_t smem_u32(const void* p) {
    uint32_t a;
    asm("{ .reg .u64 t; cvta.to.shared.u64 t, %1; cvt.u32.u64 %0, t; }" : "=r"(a) : "l"(p));
    return a;
}

__device__ __forceinline__ void ldmatrix_x4(uint32_t& r0, uint32_t& r1,
                                            uint32_t& r2, uint32_t& r3,
                                            uint32_t saddr) {
    asm volatile("ldmatrix.sync.aligned.m8n8.x4.shared.b16 {%0,%1,%2,%3}, [%4];"
                 : "=r"(r0), "=r"(r1), "=r"(r2), "=r"(r3) : "r"(saddr));
}

__device__ __forceinline__ float2 unpack_f16x2(uint32_t v) {
    float2 r;
    asm("{ .reg .f16 lo, hi;\n\t"
        "  mov.b32 {lo, hi}, %2;\n\t"
        "  cvt.f32.f16 %0, lo;\n\t"
        "  cvt.f32.f16 %1, hi; }"
        : "=f"(r.x), "=f"(r.y) : "r"(v));
    return r;
}

#define MMA4(d, a0, a1, a2, a3, b0, b1)                                      \
    asm("mma.sync.aligned.m16n8k16.row.col.f32.f16.f16.f32 "                 \
        "{%0,%1,%2,%3},{%4,%5,%6,%7},{%8,%9},{%0,%1,%2,%3};"                 \
        : "+f"((d)[0]), "+f"((d)[1]), "+f"((d)[2]), "+f"((d)[3])             \
        : "r"(a0), "r"(a1), "r"(a2), "r"(a3), "r"(b0), "r"(b1))

__global__ void __launch_bounds__(NTHREADS, 2)
iwht2_mma_kernel(const float* __restrict__ tr1, const float* __restrict__ tr2,
                 const float* __restrict__ b1,  const float* __restrict__ b2,
                 float* __restrict__ out, size_t out_stream_stride)
{
    extern __shared__ char smc[];

    // CTA = (s, b, h, khalf); khalf fastest -> sibling shares trans via L2
    const int bi    = blockIdx.x;
    const int khalf = bi & 1;
    const int h     = (bi >> 1) % NH;
    const int b     = ((bi >> 1) / NH) % BATCH;
    const int s     = bi / (2 * NH * BATCH);

    const float* tr = s ? tr2 : tr1;
    const float* bs = s ? b2  : b1;
    float* outp = out + (size_t)s * out_stream_stride;

    const int tid  = threadIdx.x;
    const int t    = tid >> 5;            // warp -> coefficient
    const int lane = tid & 31;
    const int g    = lane >> 2;           // group id (rows)
    const int tg   = lane & 3;            // thread-in-group (cols)
    char* tslot = smc + t * SLOT;

    // B fragment base: [kt][ntp][lane] uint4; this warp uses ntp = khalf*2, +1
    const char* gw = (const char*)g_wfrag
                   + (size_t)(s * T_CO + t) * 8192
                   + (size_t)(khalf * 2 * 32 + lane) * 16;

    // prefetch kt=0 B fragments; staging below hides the latency
    uint4 bc0 = *(const uint4*)(gw);
    uint4 bc1 = *(const uint4*)(gw + 512);

    // ---- stage A (warp-private): trans tile -> fp16, linear 144B rows ----
    {
        const float4* gsrc = (const float4*)(tr + (size_t)b * TRANS_B_STRIDE
                                                + (size_t)h * ROW_FLOATS
                                                + (size_t)t * TRANS_T_STRIDE);
        #pragma unroll
        for (int i = 0; i < 14; i++) {
            int idx = i * 32 + lane;           // 0..447 float4s
            int row = idx >> 4;                // 0..27
            int c4  = idx & 15;
            float4 v = __ldg(gsrc + idx);
            uint2 hh;
            hh.x = pack_f16x2(v.x, v.y);       // cols 4c4, 4c4+1
            hh.y = pack_f16x2(v.z, v.w);       // cols 4c4+2, 4c4+3
            *(uint2*)(tslot + row * AROW + c4 * 8) = hh;
        }
    }
    __syncwarp();

    // ---- GEMM: D(28x32slice) = A(28x64 fp16) x B(64x32slice fp16) ----
    float acc[2][4][4];
    #pragma unroll
    for (int mt = 0; mt < 2; mt++)
        #pragma unroll
        for (int nt = 0; nt < 4; nt++)
            #pragma unroll
            for (int j = 0; j < 4; j++) acc[mt][nt][j] = 0.0f;

    const uint32_t abase0 = smem_u32(tslot)
                          + ((lane & 7) + ((lane >> 3) & 1) * 8) * AROW
                          + ((lane >> 4)) * 16;
    const uint32_t abase1 = abase0 + 16 * AROW;

    #pragma unroll 1
    for (int kt = 0; kt < 4; kt++) {
        uint32_t a00, a01, a02, a03, a10, a11, a12, a13;
        ldmatrix_x4(a00, a01, a02, a03, abase0 + kt * 32);
        ldmatrix_x4(a10, a11, a12, a13, abase1 + kt * 32);

        MMA4(acc[0][0], a00, a01, a02, a03, bc0.x, bc0.y);
        MMA4(acc[1][0], a10, a11, a12, a13, bc0.x, bc0.y);
        MMA4(acc[0][1], a00, a01, a02, a03, bc0.z, bc0.w);
        MMA4(acc[1][1], a10, a11, a12, a13, bc0.z, bc0.w);
        MMA4(acc[0][2], a00, a01, a02, a03, bc1.x, bc1.y);
        MMA4(acc[1][2], a10, a11, a12, a13, bc1.x, bc1.y);
        MMA4(acc[0][3], a00, a01, a02, a03, bc1.z, bc1.w);
        MMA4(acc[1][3], a10, a11, a12, a13, bc1.z, bc1.w);

        if (kt < 3) {
            bc0 = *(const uint4*)(gw + (kt + 1) * 2048);
            bc1 = *(const uint4*)(gw + (kt + 1) * 2048 + 512);
        }
    }

    __syncwarp();

    // ---- write D (fp16 packed) into mix slot (warp-private reuse) ----
    #pragma unroll
    for (int mt = 0; mt < 2; mt++) {
        #pragma unroll
        for (int nt = 0; nt < 4; nt++) {
            int row0 = mt * 16 + g;
            int kp   = nt * 4 + tg;               // 0..15 within the khalf slice
            *(uint32_t*)(tslot + row0 * MIX_ROW + kp * 4) =
                pack_f16x2(acc[mt][nt][0], acc[mt][nt][1]);
            int row1 = row0 + 8;
            if (row1 < 28)
                *(uint32_t*)(tslot + row1 * MIX_ROW + kp * 4) =
                    pack_f16x2(acc[mt][nt][2], acc[mt][nt][3]);
        }
    }
    __syncthreads();

    // ---- combine: inverse 2D 4-pt WHT over t = 4u+v, scale 1/16, + bias ----
    if (tid < 448) {                       // w(28) x kpair(16)
        const int wrow = tid >> 4;
        const int kp   = tid & 15;

        float2 m[16];
        #pragma unroll
        for (int tt = 0; tt < 16; tt++)
            m[tt] = unpack_f16x2(*(const uint32_t*)(smc + tt * SLOT
                                                    + wrow * MIX_ROW + kp * 4));

        #pragma unroll
        for (int u = 0; u < 4; u++) {
            float2 m0 = m[4*u], m1 = m[4*u+1], m2 = m[4*u+2], m3 = m[4*u+3];
            float2 s0 = f2add(m0, m1), d0 = f2sub(m0, m1);
            float2 s1 = f2add(m2, m3), d1 = f2sub(m2, m3);
            m[4*u + 0] = f2add(s0, s1);
            m[4*u + 1] = f2add(d0, d1);
            m[4*u + 2] = f2sub(s0, s1);
            m[4*u + 3] = f2sub(d0, d1);
        }

        const float2 bv = ((const float2*)bs)[khalf * 16 + kp];
        float* op = outp + (size_t)b * (112 * 112 * 64)
                         + (size_t)h * (4 * 112 * 64)
                         + (size_t)wrow * (4 * 64)
                         + khalf * 32 + 2 * kp;

        #pragma unroll
        for (int j = 0; j < 4; j++) {
            float2 r0 = m[j], r1 = m[4 + j], r2 = m[8 + j], r3 = m[12 + j];
            float2 s0 = f2add(r0, r1), d0 = f2sub(r0, r1);
            float2 s1 = f2add(r2, r3), d1 = f2sub(r2, r3);
            float2 o0 = f2add(s0, s1);
            float2 o1 = f2add(d0, d1);
            float2 o2 = f2sub(s0, s1);
            float2 o3 = f2sub(d0, d1);
            float2 v0 = make_float2(fmaf(o0.x, 0.0625f, bv.x), fmaf(o0.y, 0.0625f, bv.y));
            float2 v1 = make_float2(fmaf(o1.x, 0.0625f, bv.x), fmaf(o1.y, 0.0625f, bv.y));
            float2 v2 = make_float2(fmaf(o2.x, 0.0625f, bv.x), fmaf(o2.y, 0.0625f, bv.y));
            float2 v3 = make_float2(fmaf(o3.x, 0.0625f, bv.x), fmaf(o3.y, 0.0625f, bv.y));
            *reinterpret_cast<float2*>(op + 0 * 7168 + j * 64) = v0;
            *reinterpret_cast<float2*>(op + 1 * 7168 + j * 64) = v1;
            *reinterpret_cast<float2*>(op + 2 * 7168 + j * 64) = v2;
            *reinterpret_cast<float2*>(op + 3 * 7168 + j * 64) = v3;
        }
    }
}

extern "C" void kernel_launch(void* const* d_in, const int* in_sizes, int n_in,
                              void* d_out, int out_size) {
    (void)in_sizes; (void)n_in;
    const float* tr1 = (const float*)d_in[0];
    const float* tr2 = (const float*)d_in[1];
    const float* w1  = (const float*)d_in[2];
    const float* w2  = (const float*)d_in[3];
    const float* b1  = (const float*)d_in[4];
    const float* b2  = (const float*)d_in[5];
    float* out = (float*)d_out;

    prep_weights<<<32, 256>>>(w1, w2);

    cudaFuncSetAttribute(iwht2_mma_kernel,
                         cudaFuncAttributeMaxDynamicSharedMemorySize, SMEM_BYTES);
    size_t stream_stride = (size_t)out_size / 2;   // out1 then out2
    iwht2_mma_kernel<<<2 * BATCH * NH * 2, NTHREADS, SMEM_BYTES>>>(
        tr1, tr2, b1, b2, out, stream_stride);
}